// round 1
// baseline (speedup 1.0000x reference)
#include <cuda_runtime.h>
#include <cuda_bf16.h>
#include <cstdint>

#define N_NODES 100000
#define N_EDGES 1000000
#define D 64
#define NEG_SLOPE 0.01f

// ---------------- scratch (no allocations allowed) ----------------
__device__ float g_degO[N_NODES];
__device__ float g_degI[N_NODES];
__device__ float g_oisq[N_NODES];
__device__ float g_iisq[N_NODES];
__device__ float g_agg[(size_t)N_NODES * D];
__device__ float g_h1 [(size_t)N_NODES * D];

// ---------------- zero scratch (runs every replay) ----------------
__global__ void k_zero() {
    size_t i = (size_t)blockIdx.x * blockDim.x + threadIdx.x;
    float4 z = make_float4(0.f, 0.f, 0.f, 0.f);
    if (i < (size_t)N_NODES * D / 4) ((float4*)g_agg)[i] = z;
    if (i < N_NODES) { g_degO[i] = 0.f; g_degI[i] = 0.f; }
}

// ---------------- degree counts ----------------
__global__ void k_deg(const int* __restrict__ src, const int* __restrict__ dst) {
    int e = blockIdx.x * blockDim.x + threadIdx.x;
    if (e >= N_EDGES) return;
    atomicAdd(&g_degO[src[e]], 1.f);   // no-return use -> RED
    atomicAdd(&g_degI[dst[e]], 1.f);
}

__global__ void k_isqrt() {
    int n = blockIdx.x * blockDim.x + threadIdx.x;
    if (n >= N_NODES) return;
    g_oisq[n] = rsqrtf(fmaxf(g_degO[n], 1.f));
    g_iisq[n] = rsqrtf(fmaxf(g_degI[n], 1.f));
}

// ---------------- scatter-add: agg[dst] += feat[src] (*out_isqrt[src] if SCALE) ----
// 16 threads per edge, float4 each (64 floats). Vectorized no-return reduction.
__device__ __forceinline__ void red_add_v4(float* p, float4 v) {
    asm volatile("red.global.add.v4.f32 [%0], {%1, %2, %3, %4};"
                 :: "l"(__cvta_generic_to_global(p)),
                    "f"(v.x), "f"(v.y), "f"(v.z), "f"(v.w)
                 : "memory");
}

template <bool SCALE>
__global__ void k_scatter(const float* __restrict__ feat,
                          const int* __restrict__ src,
                          const int* __restrict__ dst) {
    __shared__ int ss[16], sd[16];
    int t = threadIdx.x;
    long long e0 = (long long)blockIdx.x * 16;
    if (t < 16) {
        long long e = e0 + t;
        if (e < N_EDGES) ss[t] = src[e];
    } else if (t < 32) {
        long long e = e0 + (t - 16);
        if (e < N_EDGES) sd[t - 16] = dst[e];
    }
    __syncthreads();

    int g = t >> 4, lane = t & 15;
    long long e = e0 + g;
    if (e >= N_EDGES) return;
    int s = ss[g], d = sd[g];

    const float* fp = SCALE ? feat : g_h1;
    float4 v = __ldg((const float4*)fp + (size_t)s * 16 + lane);
    if (SCALE) {
        float sc = __ldg(&g_oisq[s]);
        v.x *= sc; v.y *= sc; v.z *= sc; v.w *= sc;
    }
    red_add_v4(g_agg + ((size_t)d * 64 + lane * 4), v);
}

// ---------------- layer transform: y = lrelu(agg*iisq @ W + b) ----------------
// 64 nodes/block, 256 threads, 4x4 register tile. Layer1 stores y*oisq to g_h1.
__global__ void k_transform1(const float* __restrict__ W, const float* __restrict__ b) {
    __shared__ float sW[D * D];
    __shared__ float sV[64][D + 4];
    int tid = threadIdx.x;
    int base = blockIdx.x * 64;

    for (int i = tid; i < D * D; i += 256) sW[i] = W[i];
    for (int i = tid; i < 64 * D; i += 256) {
        int n = i >> 6, k = i & 63;
        int gn = base + n;
        float v = 0.f;
        if (gn < N_NODES) {
            size_t idx = (size_t)gn * D + k;
            float a = g_agg[idx];
            g_agg[idx] = 0.f;                 // re-zero for layer-2 reuse
            v = a * __ldg(&g_iisq[gn]);
        }
        sV[n][k] = v;
    }
    __syncthreads();

    int nq = tid >> 4, oq = tid & 15;
    float acc[4][4];
#pragma unroll
    for (int i = 0; i < 4; i++)
#pragma unroll
        for (int j = 0; j < 4; j++) acc[i][j] = 0.f;

#pragma unroll
    for (int k = 0; k < D; k++) {
        float4 w = *(const float4*)&sW[k * D + oq * 4];
#pragma unroll
        for (int i = 0; i < 4; i++) {
            float v = sV[nq * 4 + i][k];
            acc[i][0] += v * w.x; acc[i][1] += v * w.y;
            acc[i][2] += v * w.z; acc[i][3] += v * w.w;
        }
    }

    float b4[4] = {b[oq*4+0], b[oq*4+1], b[oq*4+2], b[oq*4+3]};
#pragma unroll
    for (int i = 0; i < 4; i++) {
        int gn = base + nq * 4 + i;
        if (gn >= N_NODES) continue;
        float sc = __ldg(&g_oisq[gn]);
        float4 o;
        float y0 = acc[i][0] + b4[0]; y0 = (y0 > 0.f) ? y0 : NEG_SLOPE * y0;
        float y1 = acc[i][1] + b4[1]; y1 = (y1 > 0.f) ? y1 : NEG_SLOPE * y1;
        float y2 = acc[i][2] + b4[2]; y2 = (y2 > 0.f) ? y2 : NEG_SLOPE * y2;
        float y3 = acc[i][3] + b4[3]; y3 = (y3 > 0.f) ? y3 : NEG_SLOPE * y3;
        o.x = y0 * sc; o.y = y1 * sc; o.z = y2 * sc; o.w = y3 * sc;
        *(float4*)&g_h1[(size_t)gn * D + oq * 4] = o;
    }
}

// ---------------- final: h2 = lrelu(agg*iisq @ W2 + b2); out = h2 @ Wc + bc ----
__global__ void k_final(const float* __restrict__ W2, const float* __restrict__ b2,
                        const float* __restrict__ Wc, const float* __restrict__ bc,
                        float* __restrict__ out) {
    __shared__ float sW[D * D];
    __shared__ float sV[64][D + 4];
    __shared__ float sWc[D * 2];
    int tid = threadIdx.x;
    int base = blockIdx.x * 64;

    for (int i = tid; i < D * D; i += 256) sW[i] = W2[i];
    if (tid < D * 2) sWc[tid] = Wc[tid];
    for (int i = tid; i < 64 * D; i += 256) {
        int n = i >> 6, k = i & 63;
        int gn = base + n;
        float v = 0.f;
        if (gn < N_NODES) v = g_agg[(size_t)gn * D + k] * __ldg(&g_iisq[gn]);
        sV[n][k] = v;
    }
    __syncthreads();

    int nq = tid >> 4, oq = tid & 15;
    float acc[4][4];
#pragma unroll
    for (int i = 0; i < 4; i++)
#pragma unroll
        for (int j = 0; j < 4; j++) acc[i][j] = 0.f;

#pragma unroll
    for (int k = 0; k < D; k++) {
        float4 w = *(const float4*)&sW[k * D + oq * 4];
#pragma unroll
        for (int i = 0; i < 4; i++) {
            float v = sV[nq * 4 + i][k];
            acc[i][0] += v * w.x; acc[i][1] += v * w.y;
            acc[i][2] += v * w.z; acc[i][3] += v * w.w;
        }
    }
    __syncthreads();   // all sV reads done before overwrite

    float b4[4] = {b2[oq*4+0], b2[oq*4+1], b2[oq*4+2], b2[oq*4+3]};
#pragma unroll
    for (int i = 0; i < 4; i++) {
#pragma unroll
        for (int j = 0; j < 4; j++) {
            float y = acc[i][j] + b4[j];
            y = (y > 0.f) ? y : NEG_SLOPE * y;
            sV[nq * 4 + i][oq * 4 + j] = y;
        }
    }
    __syncthreads();

    if (tid < 128) {
        int n = tid >> 1, c = tid & 1;
        int gn = base + n;
        if (gn < N_NODES) {
            float s = bc[c];
#pragma unroll
            for (int k = 0; k < D; k++) s += sV[n][k] * sWc[k * 2 + c];
            out[(size_t)gn * 2 + c] = s;
        }
    }
}

// ---------------- launch ----------------
extern "C" void kernel_launch(void* const* d_in, const int* in_sizes, int n_in,
                              void* d_out, int out_size) {
    const float* x   = (const float*)d_in[0];
    const int*   src = (const int*)  d_in[1];
    const int*   dst = (const int*)  d_in[2];
    const float* W1  = (const float*)d_in[3];
    const float* b1  = (const float*)d_in[4];
    const float* W2  = (const float*)d_in[5];
    const float* b2  = (const float*)d_in[6];
    const float* Wc  = (const float*)d_in[7];
    const float* bc  = (const float*)d_in[8];
    float* out = (float*)d_out;

    const int zeroElems = N_NODES * D / 4;           // 1.6M float4
    k_zero<<<(zeroElems + 255) / 256, 256>>>();
    k_deg<<<(N_EDGES + 255) / 256, 256>>>(src, dst);
    k_isqrt<<<(N_NODES + 255) / 256, 256>>>();

    k_scatter<true><<<(N_EDGES + 15) / 16, 256>>>(x, src, dst);
    k_transform1<<<(N_NODES + 63) / 64, 256>>>(W1, b1);
    k_scatter<false><<<(N_EDGES + 15) / 16, 256>>>(nullptr, src, dst);
    k_final<<<(N_NODES + 63) / 64, 256>>>(W2, b2, Wc, bc, out);
}

// round 2
// speedup vs baseline: 2.0698x; 2.0698x over previous
#include <cuda_runtime.h>
#include <cuda_bf16.h>
#include <cstdint>

#define N_NODES 100000
#define N_EDGES 1000000
#define D 64
#define NEG_SLOPE 0.01f
#define SCAN_BLK 512
#define N_SCAN_BLKS ((N_NODES + SCAN_BLK - 1) / SCAN_BLK)   // 196

// ---------------- scratch (no allocations allowed) ----------------
__device__ int   g_degOi[N_NODES];
__device__ int   g_degIi[N_NODES];
__device__ float g_oisq [N_NODES];
__device__ float g_iisq [N_NODES];
__device__ int   g_rowstart[N_NODES];     // partial (block-local) exclusive scan
__device__ int   g_bsum[256];             // per-block sums
__device__ int   g_boff[256];             // exclusive scan of block sums
__device__ int   g_rowptr[N_NODES];       // final CSR row start
__device__ int   g_cursor[N_NODES];       // fill cursors
__device__ int   g_esrc[N_EDGES];         // CSR column (src) array
__device__ float g_h1[(size_t)N_NODES * D];

// ---------------- zero degree counters ----------------
__global__ void k_zero() {
    int i = blockIdx.x * blockDim.x + threadIdx.x;
    if (i < N_NODES) { g_degOi[i] = 0; g_degIi[i] = 0; }
}

// ---------------- degree histogram ----------------
__global__ void k_deg(const int* __restrict__ src, const int* __restrict__ dst) {
    int e = blockIdx.x * blockDim.x + threadIdx.x;
    if (e >= N_EDGES) return;
    atomicAdd(&g_degOi[src[e]], 1);
    atomicAdd(&g_degIi[dst[e]], 1);
}

// ---------------- scan stage 1: block-local exclusive scan of in-degrees ------
__global__ void k_scan1() {
    __shared__ int tmp[SCAN_BLK];
    int t = threadIdx.x, b = blockIdx.x;
    int i = b * SCAN_BLK + t;
    int v = (i < N_NODES) ? g_degIi[i] : 0;
    tmp[t] = v;
    __syncthreads();
#pragma unroll
    for (int off = 1; off < SCAN_BLK; off <<= 1) {
        int a = (t >= off) ? tmp[t - off] : 0;
        __syncthreads();
        tmp[t] += a;
        __syncthreads();
    }
    if (i < N_NODES) g_rowstart[i] = tmp[t] - v;     // exclusive
    if (t == SCAN_BLK - 1) g_bsum[b] = tmp[t];
}

// ---------------- scan stage 2: scan of block sums (1 block) ----------------
__global__ void k_scan2() {
    __shared__ int tmp[256];
    int t = threadIdx.x;
    int v = (t < N_SCAN_BLKS) ? g_bsum[t] : 0;
    tmp[t] = v;
    __syncthreads();
#pragma unroll
    for (int off = 1; off < 256; off <<= 1) {
        int a = (t >= off) ? tmp[t - off] : 0;
        __syncthreads();
        tmp[t] += a;
        __syncthreads();
    }
    if (t < N_SCAN_BLKS) g_boff[t] = tmp[t] - v;     // exclusive
}

// ---------------- scan stage 3: finalize rowptr/cursor + norms ----------------
__global__ void k_scan3() {
    int i = blockIdx.x * blockDim.x + threadIdx.x;
    if (i >= N_NODES) return;
    int row = g_rowstart[i] + g_boff[i >> 9];
    g_rowptr[i] = row;
    g_cursor[i] = row;
    g_oisq[i] = rsqrtf((float)max(g_degOi[i], 1));
    g_iisq[i] = rsqrtf((float)max(g_degIi[i], 1));
}

// ---------------- CSR fill ----------------
__global__ void k_fill(const int* __restrict__ src, const int* __restrict__ dst) {
    int e = blockIdx.x * blockDim.x + threadIdx.x;
    if (e >= N_EDGES) return;
    int pos = atomicAdd(&g_cursor[dst[e]], 1);
    g_esrc[pos] = src[e];
}

// =====================================================================
// Fused layer kernels: CSR aggregate (4 threads/node) -> smem -> GEMM
// Block: 256 threads, 64 nodes.
// =====================================================================

// Layer 1: agg = sum_e x[src]*oisq[src]; v = agg*iisq; h1 = lrelu(v@W1+b1)*oisq
__global__ void __launch_bounds__(256) k_layer1(
    const float* __restrict__ x, const float* __restrict__ W,
    const float* __restrict__ b)
{
    __shared__ float sW[D * D];
    __shared__ float sV[64][D + 4];
    int tid = threadIdx.x;
    int base = blockIdx.x * 64;

    for (int i = tid; i < D * D; i += 256) sW[i] = W[i];

    // ---- phase A: aggregate. group g (4 threads), lane l handles f = l*4+j*16
    int g = tid >> 2, l = tid & 3;
    int gn = base + g;
    float4 a0 = {0,0,0,0}, a1 = {0,0,0,0}, a2 = {0,0,0,0}, a3 = {0,0,0,0};
    if (gn < N_NODES) {
        int start = g_rowptr[gn];
        int deg   = g_degIi[gn];
        for (int i = 0; i < deg; i++) {
            int s = __ldg(&g_esrc[start + i]);
            float sc = __ldg(&g_oisq[s]);
            const float4* p = (const float4*)(x + (size_t)s * D);
            float4 v0 = __ldg(p + l + 0);
            float4 v1 = __ldg(p + l + 4);
            float4 v2 = __ldg(p + l + 8);
            float4 v3 = __ldg(p + l + 12);
            a0.x += sc*v0.x; a0.y += sc*v0.y; a0.z += sc*v0.z; a0.w += sc*v0.w;
            a1.x += sc*v1.x; a1.y += sc*v1.y; a1.z += sc*v1.z; a1.w += sc*v1.w;
            a2.x += sc*v2.x; a2.y += sc*v2.y; a2.z += sc*v2.z; a2.w += sc*v2.w;
            a3.x += sc*v3.x; a3.y += sc*v3.y; a3.z += sc*v3.z; a3.w += sc*v3.w;
        }
        float fi = g_iisq[gn];
        a0.x*=fi; a0.y*=fi; a0.z*=fi; a0.w*=fi;
        a1.x*=fi; a1.y*=fi; a1.z*=fi; a1.w*=fi;
        a2.x*=fi; a2.y*=fi; a2.z*=fi; a2.w*=fi;
        a3.x*=fi; a3.y*=fi; a3.z*=fi; a3.w*=fi;
    }
    *(float4*)&sV[g][l*4 +  0] = a0;
    *(float4*)&sV[g][l*4 + 16] = a1;
    *(float4*)&sV[g][l*4 + 32] = a2;
    *(float4*)&sV[g][l*4 + 48] = a3;
    __syncthreads();

    // ---- phase B: GEMM 64x64 @ 64x64, 4x4 register tile
    int nq = tid >> 4, oq = tid & 15;
    float acc[4][4];
#pragma unroll
    for (int i = 0; i < 4; i++)
#pragma unroll
        for (int j = 0; j < 4; j++) acc[i][j] = 0.f;
#pragma unroll
    for (int k = 0; k < D; k++) {
        float4 w = *(const float4*)&sW[k * D + oq * 4];
#pragma unroll
        for (int i = 0; i < 4; i++) {
            float v = sV[nq * 4 + i][k];
            acc[i][0] += v * w.x; acc[i][1] += v * w.y;
            acc[i][2] += v * w.z; acc[i][3] += v * w.w;
        }
    }
    float b4[4] = {b[oq*4+0], b[oq*4+1], b[oq*4+2], b[oq*4+3]};
#pragma unroll
    for (int i = 0; i < 4; i++) {
        int on = base + nq * 4 + i;
        if (on >= N_NODES) continue;
        float sc = __ldg(&g_oisq[on]);        // pre-scale for layer-2 gather
        float4 o;
        float y0 = acc[i][0]+b4[0]; y0 = (y0>0.f)?y0:NEG_SLOPE*y0;
        float y1 = acc[i][1]+b4[1]; y1 = (y1>0.f)?y1:NEG_SLOPE*y1;
        float y2 = acc[i][2]+b4[2]; y2 = (y2>0.f)?y2:NEG_SLOPE*y2;
        float y3 = acc[i][3]+b4[3]; y3 = (y3>0.f)?y3:NEG_SLOPE*y3;
        o.x = y0*sc; o.y = y1*sc; o.z = y2*sc; o.w = y3*sc;
        *(float4*)&g_h1[(size_t)on * D + oq * 4] = o;
    }
}

// Layer 2 + classifier: agg = sum_e h1[src] (pre-scaled); v = agg*iisq;
// h2 = lrelu(v@W2+b2); out = h2@Wc+bc
__global__ void __launch_bounds__(256) k_layer2(
    const float* __restrict__ W2, const float* __restrict__ b2,
    const float* __restrict__ Wc, const float* __restrict__ bc,
    float* __restrict__ out)
{
    __shared__ float sW[D * D];
    __shared__ float sV[64][D + 4];
    __shared__ float sWc[D * 2];
    int tid = threadIdx.x;
    int base = blockIdx.x * 64;

    for (int i = tid; i < D * D; i += 256) sW[i] = W2[i];
    if (tid < D * 2) sWc[tid] = Wc[tid];

    int g = tid >> 2, l = tid & 3;
    int gn = base + g;
    float4 a0 = {0,0,0,0}, a1 = {0,0,0,0}, a2 = {0,0,0,0}, a3 = {0,0,0,0};
    if (gn < N_NODES) {
        int start = g_rowptr[gn];
        int deg   = g_degIi[gn];
        for (int i = 0; i < deg; i++) {
            int s = __ldg(&g_esrc[start + i]);
            const float4* p = (const float4*)(g_h1 + (size_t)s * D);
            float4 v0 = __ldg(p + l + 0);
            float4 v1 = __ldg(p + l + 4);
            float4 v2 = __ldg(p + l + 8);
            float4 v3 = __ldg(p + l + 12);
            a0.x += v0.x; a0.y += v0.y; a0.z += v0.z; a0.w += v0.w;
            a1.x += v1.x; a1.y += v1.y; a1.z += v1.z; a1.w += v1.w;
            a2.x += v2.x; a2.y += v2.y; a2.z += v2.z; a2.w += v2.w;
            a3.x += v3.x; a3.y += v3.y; a3.z += v3.z; a3.w += v3.w;
        }
        float fi = g_iisq[gn];
        a0.x*=fi; a0.y*=fi; a0.z*=fi; a0.w*=fi;
        a1.x*=fi; a1.y*=fi; a1.z*=fi; a1.w*=fi;
        a2.x*=fi; a2.y*=fi; a2.z*=fi; a2.w*=fi;
        a3.x*=fi; a3.y*=fi; a3.z*=fi; a3.w*=fi;
    }
    *(float4*)&sV[g][l*4 +  0] = a0;
    *(float4*)&sV[g][l*4 + 16] = a1;
    *(float4*)&sV[g][l*4 + 32] = a2;
    *(float4*)&sV[g][l*4 + 48] = a3;
    __syncthreads();

    int nq = tid >> 4, oq = tid & 15;
    float acc[4][4];
#pragma unroll
    for (int i = 0; i < 4; i++)
#pragma unroll
        for (int j = 0; j < 4; j++) acc[i][j] = 0.f;
#pragma unroll
    for (int k = 0; k < D; k++) {
        float4 w = *(const float4*)&sW[k * D + oq * 4];
#pragma unroll
        for (int i = 0; i < 4; i++) {
            float v = sV[nq * 4 + i][k];
            acc[i][0] += v * w.x; acc[i][1] += v * w.y;
            acc[i][2] += v * w.z; acc[i][3] += v * w.w;
        }
    }
    __syncthreads();   // all sV reads done before overwrite

    float b4[4] = {b2[oq*4+0], b2[oq*4+1], b2[oq*4+2], b2[oq*4+3]};
#pragma unroll
    for (int i = 0; i < 4; i++) {
#pragma unroll
        for (int j = 0; j < 4; j++) {
            float y = acc[i][j] + b4[j];
            y = (y > 0.f) ? y : NEG_SLOPE * y;
            sV[nq * 4 + i][oq * 4 + j] = y;
        }
    }
    __syncthreads();

    if (tid < 128) {
        int n = tid >> 1, c = tid & 1;
        int on = base + n;
        if (on < N_NODES) {
            float s = bc[c];
#pragma unroll
            for (int k = 0; k < D; k++) s += sV[n][k] * sWc[k * 2 + c];
            out[(size_t)on * 2 + c] = s;
        }
    }
}

// ---------------- launch ----------------
extern "C" void kernel_launch(void* const* d_in, const int* in_sizes, int n_in,
                              void* d_out, int out_size) {
    const float* x   = (const float*)d_in[0];
    const int*   src = (const int*)  d_in[1];
    const int*   dst = (const int*)  d_in[2];
    const float* W1  = (const float*)d_in[3];
    const float* b1  = (const float*)d_in[4];
    const float* W2  = (const float*)d_in[5];
    const float* b2  = (const float*)d_in[6];
    const float* Wc  = (const float*)d_in[7];
    const float* bc  = (const float*)d_in[8];
    float* out = (float*)d_out;

    k_zero <<<(N_NODES + 255) / 256, 256>>>();
    k_deg  <<<(N_EDGES + 255) / 256, 256>>>(src, dst);
    k_scan1<<<N_SCAN_BLKS, SCAN_BLK>>>();
    k_scan2<<<1, 256>>>();
    k_scan3<<<(N_NODES + 255) / 256, 256>>>();
    k_fill <<<(N_EDGES + 255) / 256, 256>>>(src, dst);

    k_layer1<<<(N_NODES + 63) / 64, 256>>>(x, W1, b1);
    k_layer2<<<(N_NODES + 63) / 64, 256>>>(W2, b2, Wc, bc, out);
}